// round 1
// baseline (speedup 1.0000x reference)
#include <cuda_runtime.h>
#include <math.h>

#define VOCAB  32000
#define EMBED  300
#define HIDDEN 1024
#define POL    3
#define BS     64
#define SEQ    512
#define G4H    (4 * HIDDEN)

#define NBLK   128   // persistent CTAs in recurrence (<=148 SMs -> all co-resident)
#define CPB    32    // gate columns per block (8 h-cols x 4 gates)
#define HPB    8     // h columns per block
#define KC     60    // K-chunk for the xU GEMM (300 = 5*60)

// ---------------- scratch (device globals; no allocations allowed) ----------------
__device__ float g_xu[(size_t)SEQ * G4H * BS];   // [s][jp][b]  512 MB
__device__ float g_Vr[(size_t)HIDDEN * G4H];     // [p][k][cc]  16 MB (permuted V)
__device__ float g_Ur[(size_t)EMBED * G4H];      // [e][jp]     4.9 MB (permuted U)
__device__ float g_br[G4H];                      // [jp]        permuted bias
__device__ float g_h[2][HIDDEN * BS];            // k-major: h[buf][hcol][b]
__device__ unsigned g_bar_arrive;
__device__ unsigned g_bar_gen;

// jp <-> original column mapping:
//   jp = p*32 + cc,  cc = g*8 + l,  original j = g*1024 + 8*p + l

// ---------------- prep: permute weights, zero h, reset barrier ----------------
__global__ void prep_kernel(const float* __restrict__ Vi, const float* __restrict__ Vf,
                            const float* __restrict__ Vc, const float* __restrict__ Vo,
                            const float* __restrict__ Ui, const float* __restrict__ Uf,
                            const float* __restrict__ Uc, const float* __restrict__ Uo,
                            const float* __restrict__ bi, const float* __restrict__ bf,
                            const float* __restrict__ bc, const float* __restrict__ bo)
{
    size_t idx0 = (size_t)blockIdx.x * blockDim.x + threadIdx.x;
    size_t stride = (size_t)gridDim.x * blockDim.x;
    if (idx0 == 0) { g_bar_arrive = 0u; g_bar_gen = 0u; }

    // Vr[(p*1024 + k)*32 + cc] = V_g[k][8p + l]
    for (size_t i = idx0; i < (size_t)HIDDEN * G4H; i += stride) {
        int cc = (int)(i & 31);
        size_t t = i >> 5;
        int k = (int)(t & 1023);
        int p = (int)(t >> 10);
        int g = cc >> 3, l = cc & 7;
        int col = 8 * p + l;
        const float* V = (g == 0) ? Vi : (g == 1) ? Vf : (g == 2) ? Vc : Vo;
        g_Vr[i] = V[(size_t)k * HIDDEN + col];
    }
    // Ur[e*4096 + jp] = U_g[e][8p + l]
    for (size_t i = idx0; i < (size_t)EMBED * G4H; i += stride) {
        int jp = (int)(i % G4H);
        size_t e = i / G4H;
        int p = jp >> 5, cc = jp & 31, g = cc >> 3, l = cc & 7;
        int col = 8 * p + l;
        const float* U = (g == 0) ? Ui : (g == 1) ? Uf : (g == 2) ? Uc : Uo;
        g_Ur[i] = U[e * HIDDEN + col];
    }
    for (size_t i = idx0; i < (size_t)G4H; i += stride) {
        int jp = (int)i;
        int p = jp >> 5, cc = jp & 31, g = cc >> 3, l = cc & 7;
        const float* b = (g == 0) ? bi : (g == 1) ? bf : (g == 2) ? bc : bo;
        g_br[i] = b[8 * p + l];
    }
    for (size_t i = idx0; i < (size_t)HIDDEN * BS; i += stride) g_h[0][i] = 0.0f;
}

// ---------------- xU: fused embed-gather GEMM  out[s][jp][b] = x@U + b ----------------
__global__ void __launch_bounds__(256) xu_kernel(const int* __restrict__ text,
                                                 const float* __restrict__ embed)
{
    __shared__ __align__(16) float Ua[KC][68];   // [e][jp-in-tile]
    __shared__ __align__(16) float Xb[KC][68];   // [e][b]
    __shared__ int rows[BS];

    const int s = blockIdx.y;
    const int jpBase = blockIdx.x * 64;
    const int tid = threadIdx.x;

    if (tid < BS) rows[tid] = text[tid * SEQ + s];
    __syncthreads();

    const int tx = tid & 15, ty = tid >> 4;
    const int jp0 = tx * 4, b0 = ty * 4;

    float acc[4][4];
#pragma unroll
    for (int i = 0; i < 4; i++)
#pragma unroll
        for (int j = 0; j < 4; j++) acc[i][j] = 0.0f;

    for (int e0 = 0; e0 < EMBED; e0 += KC) {
        for (int idx = tid; idx < KC * 64; idx += 256) {
            int e = idx >> 6, c = idx & 63;
            Ua[e][c] = g_Ur[(size_t)(e0 + e) * G4H + jpBase + c];
        }
        for (int idx = tid; idx < KC * 64; idx += 256) {
            int b = idx / KC, e = idx - b * KC;
            Xb[e][b] = embed[(size_t)rows[b] * EMBED + e0 + e];
        }
        __syncthreads();
#pragma unroll 4
        for (int e = 0; e < KC; e++) {
            float4 ua = *(const float4*)&Ua[e][jp0];
            float4 xb = *(const float4*)&Xb[e][b0];
            float a[4] = {ua.x, ua.y, ua.z, ua.w};
            float x4[4] = {xb.x, xb.y, xb.z, xb.w};
#pragma unroll
            for (int i = 0; i < 4; i++)
#pragma unroll
                for (int j = 0; j < 4; j++)
                    acc[i][j] = fmaf(a[i], x4[j], acc[i][j]);
        }
        __syncthreads();
    }

#pragma unroll
    for (int i = 0; i < 4; i++) {
        int jp = jpBase + jp0 + i;
        float bias = g_br[jp];
        float4 v = make_float4(acc[i][0] + bias, acc[i][1] + bias,
                               acc[i][2] + bias, acc[i][3] + bias);
        *(float4*)(g_xu + ((size_t)s * G4H + jp) * BS + b0) = v;
    }
}

// ---------------- persistent recurrence ----------------
__global__ void __launch_bounds__(256, 1) rnn_kernel()
{
    __shared__ __align__(16) float hch[128 * BS];     // staged h chunk [kk][b]  32 KB
    __shared__ __align__(16) float gbuf[CPB * 68];    // gate preacts [cc][b]    8.5 KB
    __shared__ float cst[HPB * BS];                   // cell state [l][b]       2 KB

    const int p = blockIdx.x;
    const int tid = threadIdx.x;
    const int cpair = tid & 15;
    const int bq = tid >> 4;
    const int c0 = cpair * 2;
    const int b0 = bq * 4;

    for (int i = tid; i < HPB * BS; i += 256) cst[i] = 0.0f;

    const float* __restrict__ Vrp = g_Vr + (size_t)p * HIDDEN * CPB;

    for (int t = 0; t < SEQ; t++) {
        const float* hsrc = g_h[t & 1];
        float* hdst = g_h[(t + 1) & 1];
        const float* xup = g_xu + ((size_t)t * G4H + p * CPB) * BS;

        // acc starts at xu (bias already folded in)
        float acc[2][4];
#pragma unroll
        for (int i = 0; i < 2; i++) {
            float4 v = __ldcs((const float4*)(xup + (c0 + i) * BS + b0));
            acc[i][0] = v.x; acc[i][1] = v.y; acc[i][2] = v.z; acc[i][3] = v.w;
        }

        // gates += h @ V  (K = 1024, staged in 8 chunks of 128)
        for (int kc = 0; kc < HIDDEN; kc += 128) {
            __syncthreads();
            const float4* hs4 = (const float4*)(hsrc + kc * BS);
            float4* hch4 = (float4*)hch;
#pragma unroll
            for (int i = 0; i < 8; i++)
                hch4[i * 256 + tid] = __ldcs(hs4 + i * 256 + tid);  // stream; keep V in L1
            __syncthreads();
            const float* Vk = Vrp + (size_t)kc * CPB;
#pragma unroll 4
            for (int kk = 0; kk < 128; kk++) {
                float4 hv = *(const float4*)&hch[kk * BS + b0];
                float2 vv = __ldg((const float2*)(Vk + kk * CPB + c0));
                acc[0][0] = fmaf(vv.x, hv.x, acc[0][0]);
                acc[0][1] = fmaf(vv.x, hv.y, acc[0][1]);
                acc[0][2] = fmaf(vv.x, hv.z, acc[0][2]);
                acc[0][3] = fmaf(vv.x, hv.w, acc[0][3]);
                acc[1][0] = fmaf(vv.y, hv.x, acc[1][0]);
                acc[1][1] = fmaf(vv.y, hv.y, acc[1][1]);
                acc[1][2] = fmaf(vv.y, hv.z, acc[1][2]);
                acc[1][3] = fmaf(vv.y, hv.w, acc[1][3]);
            }
        }

#pragma unroll
        for (int i = 0; i < 2; i++)
            *(float4*)&gbuf[(c0 + i) * 68 + b0] =
                make_float4(acc[i][0], acc[i][1], acc[i][2], acc[i][3]);
        __syncthreads();

        // nonlinearity + state update for this block's 8 h-columns
#pragma unroll
        for (int r = 0; r < 2; r++) {
            int idx = tid + r * 256;     // (l, b): l = idx>>6, b = idx&63
            int l = idx >> 6;
            int b = idx & 63;
            float xi = gbuf[l * 68 + b];
            float xf = gbuf[(8 + l) * 68 + b];
            float xg = gbuf[(16 + l) * 68 + b];
            float xo = gbuf[(24 + l) * 68 + b];
            float iv = 1.0f / (1.0f + __expf(-xi));
            float fv = 1.0f / (1.0f + __expf(-xf));
            float gv = tanhf(xg);
            float ov = 1.0f / (1.0f + __expf(-xo));
            float cv = fmaf(fv, cst[idx], iv * gv);
            cst[idx] = cv;
            hdst[(p * HPB + l) * BS + b] = ov * tanhf(cv);
        }
        __syncthreads();

        // ---- grid barrier (monotone generation; reset each launch by prep) ----
        if (tid == 0) {
            __threadfence();
            unsigned target = (unsigned)(t + 1);
            unsigned old = atomicAdd(&g_bar_arrive, 1u);
            if (old == target * NBLK - 1u) {
                atomicAdd(&g_bar_gen, 1u);
            } else {
                while (*((volatile unsigned*)&g_bar_gen) < target) { }
            }
            __threadfence();
        }
        __syncthreads();
    }
}

// ---------------- head: out = h_n @ W_dense + b_dense ----------------
__global__ void head_kernel(const float* __restrict__ W, const float* __restrict__ bd,
                            float* __restrict__ out)
{
    int tid = threadIdx.x;
    if (tid < BS * POL) {
        int b = tid / POL, pp = tid - b * POL;
        float s = bd[pp];
        const float* h = g_h[0];  // after 512 steps, final h lives in buffer 0
        for (int k = 0; k < HIDDEN; k++)
            s = fmaf(h[k * BS + b], W[k * POL + pp], s);
        out[tid] = s;
    }
}

// ---------------- launch ----------------
extern "C" void kernel_launch(void* const* d_in, const int* in_sizes, int n_in,
                              void* d_out, int out_size)
{
    (void)in_sizes; (void)n_in; (void)out_size;
    const int*   text  = (const int*)d_in[0];
    const float* embed = (const float*)d_in[1];
    const float* Ui = (const float*)d_in[2],  *Uf = (const float*)d_in[3];
    const float* Uc = (const float*)d_in[4],  *Uo = (const float*)d_in[5];
    const float* Vi = (const float*)d_in[6],  *Vf = (const float*)d_in[7];
    const float* Vc = (const float*)d_in[8],  *Vo = (const float*)d_in[9];
    const float* bi = (const float*)d_in[10], *bf = (const float*)d_in[11];
    const float* bc = (const float*)d_in[12], *bo = (const float*)d_in[13];
    const float* W  = (const float*)d_in[14], *bd = (const float*)d_in[15];
    float* out = (float*)d_out;

    prep_kernel<<<2048, 256>>>(Vi, Vf, Vc, Vo, Ui, Uf, Uc, Uo, bi, bf, bc, bo);

    dim3 gx(G4H / 64, SEQ);
    xu_kernel<<<gx, 256>>>(text, embed);

    rnn_kernel<<<NBLK, 256>>>();

    head_kernel<<<1, 256>>>(W, bd, out);
}